// round 2
// baseline (speedup 1.0000x reference)
#include <cuda_runtime.h>
#include <math.h>
#include <stdint.h>

// LSTM scan: B=256, T=512, D=1, H=512. W: [513, 2048], gates (i,j,f,o).
// c_new = c*sig(f+1) + sig(i)*tanh(j); h_new = tanh(c_new)*sig(o)
// Round 2: packed fma.rn.f32x2 (2x fp32 FLOP/issue), duplicated-A smem,
// cp.async double-buffered k-pipeline.

#define BATCH 256
#define TSTEPS 512
#define HDIM 512
#define GDIM 2048
#define BK 32

__device__ float g_h[2][BATCH * HDIM];
__device__ float g_c[BATCH * HDIM];

__global__ void lstm_init() {
    int n = BATCH * HDIM;
    for (int i = blockIdx.x * blockDim.x + threadIdx.x; i < n;
         i += gridDim.x * blockDim.x) {
        g_h[0][i] = 0.0f;
        g_c[i] = 0.0f;
    }
}

__device__ __forceinline__ float sigmoidf_(float v) {
    return 1.0f / (1.0f + expf(-v));
}

#define FMA2(c_, a_, b_) \
    asm("fma.rn.f32x2 %0, %1, %2, %0;" : "+l"(c_) : "l"(a_), "l"(b_))

__device__ __forceinline__ void cp4(uint32_t dst, const void* src) {
    asm volatile("cp.async.ca.shared.global [%0], [%1], 4;" :: "r"(dst), "l"(src));
}
__device__ __forceinline__ void cp16(uint32_t dst, const void* src) {
    asm volatile("cp.async.cg.shared.global [%0], [%1], 16;" :: "r"(dst), "l"(src));
}

// Tile: 32 batch rows x 128 gate cols (32 h-cols x 4 gates), BK=32.
// 256 threads, micro 4x4 (2 col-pairs). Grid (16, 8) = 128 CTAs.
__global__ void __launch_bounds__(256, 1) lstm_step(
    const float* __restrict__ x,
    const float* __restrict__ W,
    const float* __restrict__ bias,
    float* __restrict__ out,
    int t)
{
    const float* __restrict__ hprev = g_h[t & 1];
    float* __restrict__ hnext = g_h[(t + 1) & 1];

    // as2[buf][k][r] = (h, h) duplicated pair  -> 2*32*32*8  = 16 KB
    // bs [buf][k][j] gate-chunked W tile       -> 2*32*128*4 = 32 KB (48 KB total)
    __shared__ __align__(16) unsigned long long as2[2][BK][32];
    __shared__ __align__(16) float bs[2][BK][128];

    const int tid = threadIdx.x;
    const int m_base = blockIdx.y * 32;
    const int n_base = blockIdx.x * 32;
    const int ty = tid >> 5;          // 0..7
    const int tx = tid & 31;          // 0..31
    const int ty4 = ty * 4, tx4 = tx * 4;

    // ---- prefetch helpers (cp.async) ----
    auto prefetch = [&](int buf, int k0) {
        // A: duplicate each h value into an 8-byte (v,v) pair, layout [c][r]
        #pragma unroll
        for (int j = 0; j < 4; j++) {
            int e = j * 256 + tid;
            int r = e >> 5, c = e & 31;
            const float* src = &hprev[(m_base + r) * HDIM + k0 + c];
            uint32_t d = (uint32_t)__cvta_generic_to_shared(&as2[buf][c][r]);
            cp4(d, src);
            cp4(d + 4, src);
        }
        // B: bs[kr][gate*32+c] = W[1+k0+kr][gate*512 + n_base + c], 16B chunks
        #pragma unroll
        for (int j = 0; j < 4; j++) {
            int e = j * 256 + tid;
            int kr = e >> 5, ch = e & 31;
            int gate = ch >> 3, c = (ch & 7) * 4;
            const float* src = &W[(size_t)(1 + k0 + kr) * GDIM + gate * HDIM + n_base + c];
            uint32_t d = (uint32_t)__cvta_generic_to_shared(&bs[buf][kr][gate * 32 + c]);
            cp16(d, src);
        }
    };

    unsigned long long acc00 = 0, acc01 = 0, acc10 = 0, acc11 = 0;
    unsigned long long acc20 = 0, acc21 = 0, acc30 = 0, acc31 = 0;

    prefetch(0, 0);
    asm volatile("cp.async.commit_group;");

    #pragma unroll 1
    for (int kt = 0; kt < HDIM / BK; kt++) {
        const int buf = kt & 1;
        if (kt < HDIM / BK - 1) {
            prefetch(buf ^ 1, (kt + 1) * BK);
            asm volatile("cp.async.commit_group;");
            asm volatile("cp.async.wait_group 1;");
        } else {
            asm volatile("cp.async.wait_group 0;");
        }
        __syncthreads();

        #pragma unroll 8
        for (int k = 0; k < BK; k++) {
            ulonglong2 a01 = *(const ulonglong2*)&as2[buf][k][ty4];
            ulonglong2 a23 = *(const ulonglong2*)&as2[buf][k][ty4 + 2];
            ulonglong2 bv  = *(const ulonglong2*)&bs[buf][k][tx4];
            FMA2(acc00, a01.x, bv.x); FMA2(acc01, a01.x, bv.y);
            FMA2(acc10, a01.y, bv.x); FMA2(acc11, a01.y, bv.y);
            FMA2(acc20, a23.x, bv.x); FMA2(acc21, a23.x, bv.y);
            FMA2(acc30, a23.y, bv.x); FMA2(acc31, a23.y, bv.y);
        }
        __syncthreads();
    }

    // ---- stage z to smem (alias bs[0], 32x128 floats) ----
    float (*zs)[128] = bs[0];
    {
        unsigned long long a[4][2] = {{acc00, acc01}, {acc10, acc11},
                                      {acc20, acc21}, {acc30, acc31}};
        #pragma unroll
        for (int rr = 0; rr < 4; rr++)
            #pragma unroll
            for (int p = 0; p < 2; p++) {
                float lo, hi;
                asm("mov.b64 {%0,%1}, %2;" : "=f"(lo), "=f"(hi) : "l"(a[rr][p]));
                zs[ty4 + rr][tx4 + p * 2 + 0] = lo;
                zs[ty4 + rr][tx4 + p * 2 + 1] = hi;
            }
    }
    __syncthreads();

    // ---- gate fusion: 4 (batch,hcol) outputs per thread ----
    #pragma unroll
    for (int i = 0; i < 4; i++) {
        int o = i * 256 + tid;
        int r = o >> 5;
        int hc = o & 31;
        int b_row = m_base + r;
        int h_col = n_base + hc;

        float xv = x[b_row * TSTEPS + t];   // D == 1

        float zi = zs[r][hc]      + fmaf(xv, W[0 * HDIM + h_col], bias[0 * HDIM + h_col]);
        float zj = zs[r][32 + hc] + fmaf(xv, W[1 * HDIM + h_col], bias[1 * HDIM + h_col]);
        float zf = zs[r][64 + hc] + fmaf(xv, W[2 * HDIM + h_col], bias[2 * HDIM + h_col]);
        float zo = zs[r][96 + hc] + fmaf(xv, W[3 * HDIM + h_col], bias[3 * HDIM + h_col]);

        int sidx = b_row * HDIM + h_col;
        float c_old = g_c[sidx];

        float fg = sigmoidf_(zf + 1.0f);
        float ig = sigmoidf_(zi);
        float og = sigmoidf_(zo);
        float c_new = c_old * fg + ig * tanhf(zj);
        float h_new = tanhf(c_new) * og;

        g_c[sidx] = c_new;
        hnext[sidx] = h_new;
        out[(size_t)b_row * (TSTEPS * HDIM) + (size_t)t * HDIM + h_col] = h_new;
    }
}

extern "C" void kernel_launch(void* const* d_in, const int* in_sizes, int n_in,
                              void* d_out, int out_size) {
    const float* x    = (const float*)d_in[0];
    const float* W    = (const float*)d_in[1];
    const float* bias = (const float*)d_in[2];
    float* out = (float*)d_out;
    (void)in_sizes; (void)n_in; (void)out_size;

    lstm_init<<<256, 256>>>();

    dim3 grid(HDIM / 32, BATCH / 32);   // (16, 8) = 128 CTAs
    for (int t = 0; t < TSTEPS; t++) {
        lstm_step<<<grid, 256>>>(x, W, bias, out, t);
    }
}

// round 3
// speedup vs baseline: 1.5949x; 1.5949x over previous
#include <cuda_runtime.h>
#include <math.h>
#include <stdint.h>

// LSTM scan: B=256, T=512, D=1, H=512. W: [513, 2048], gates (i,j,f,o).
// Round 3: fma.rn.f32x2 fed by register packing; plain LDG->STS double buffer;
// 512 threads/CTA (16 warps) for latency hiding. Tile 32x128, micro 2x4.

#define BATCH 256
#define TSTEPS 512
#define HDIM 512
#define GDIM 2048
#define BK 32
#define NKT (HDIM / BK)   // 16 k-tiles

__device__ float g_h[2][BATCH * HDIM];
__device__ float g_c[BATCH * HDIM];

__global__ void lstm_init() {
    int n = BATCH * HDIM;
    for (int i = blockIdx.x * blockDim.x + threadIdx.x; i < n;
         i += gridDim.x * blockDim.x) {
        g_h[0][i] = 0.0f;
        g_c[i] = 0.0f;
    }
}

__device__ __forceinline__ float sigmoidf_(float v) {
    return 1.0f / (1.0f + expf(-v));
}

#define FMA2(c_, a_, b_) \
    asm("fma.rn.f32x2 %0, %1, %2, %0;" : "+l"(c_) : "l"(a_), "l"(b_))

#define PACK2(d_, s_) \
    asm("mov.b64 %0, {%1, %1};" : "=l"(d_) : "f"(s_))

// Grid (16, 8) = 128 CTAs; 512 threads. Tile: 32 batch rows x 128 gate cols.
__global__ void __launch_bounds__(512, 1) lstm_step(
    const float* __restrict__ x,
    const float* __restrict__ W,
    const float* __restrict__ bias,
    float* __restrict__ out,
    int t)
{
    const float* __restrict__ hprev = g_h[t & 1];
    float* __restrict__ hnext = g_h[(t + 1) & 1];

    __shared__ __align__(16) float as[2][BK][34];    // A^T tile, padded (8.7 KB)
    __shared__ __align__(16) float bs[2][BK][128];   // W tile, gate-chunked (32 KB)

    const int tid = threadIdx.x;
    const int m_base = blockIdx.y * 32;
    const int n_base = blockIdx.x * 32;

    const int warp = tid >> 5;            // 0..15
    const int lane = tid & 31;
    const int r0 = warp * 2;              // two consecutive batch rows
    const int lane4 = lane * 4;           // 4 gate-chunked cols

    // global-load indices (A: 2 scalars; B: 2 float4 chunks)
    const int ae0_r = tid >> 5,        ae0_c = tid & 31;
    const int ae1_r = (tid + 512) >> 5, ae1_c = (tid + 512) & 31;
    const int bq0_kr = tid >> 5;                  // == warp
    const int bq0_j = (tid & 31) * 4;
    const int bq1_kr = (tid + 512) >> 5;          // warp + 16
    const int bq1_j = bq0_j;
    const int b0_gate = bq0_j >> 5, b0_c = bq0_j & 31;

    float a_reg0, a_reg1;
    float4 b_reg0, b_reg1;

    auto ldg_tile = [&](int k0) {
        a_reg0 = hprev[(m_base + ae0_r) * HDIM + k0 + ae0_c];
        a_reg1 = hprev[(m_base + ae1_r) * HDIM + k0 + ae1_c];
        const float* wb = &W[(size_t)(1 + k0) * GDIM + n_base];
        b_reg0 = *(const float4*)&wb[(size_t)bq0_kr * GDIM + b0_gate * HDIM + b0_c];
        b_reg1 = *(const float4*)&wb[(size_t)bq1_kr * GDIM + b0_gate * HDIM + b0_c];
    };
    auto sts_tile = [&](int buf) {
        as[buf][ae0_c][ae0_r] = a_reg0;
        as[buf][ae1_c][ae1_r] = a_reg1;
        *(float4*)&bs[buf][bq0_kr][bq0_j] = b_reg0;
        *(float4*)&bs[buf][bq1_kr][bq1_j] = b_reg1;
    };

    unsigned long long acc00 = 0, acc01 = 0, acc10 = 0, acc11 = 0;

    ldg_tile(0);

    #pragma unroll 1
    for (int kt = 0; kt < NKT; kt++) {
        const int buf = kt & 1;
        sts_tile(buf);
        __syncthreads();
        if (kt < NKT - 1) ldg_tile((kt + 1) * BK);

        #pragma unroll 8
        for (int k = 0; k < BK; k++) {
            float2 a2 = *(const float2*)&as[buf][k][r0];
            ulonglong2 bv = *(const ulonglong2*)&bs[buf][k][lane4];
            unsigned long long a0p, a1p;
            PACK2(a0p, a2.x);
            PACK2(a1p, a2.y);
            FMA2(acc00, a0p, bv.x);
            FMA2(acc01, a0p, bv.y);
            FMA2(acc10, a1p, bv.x);
            FMA2(acc11, a1p, bv.y);
        }
        __syncthreads();
    }

    // ---- stage z to smem (alias bs[0]: 32 x 128 floats) ----
    float (*zs)[128] = bs[0];
    {
        float lo, hi;
        asm("mov.b64 {%0,%1}, %2;" : "=f"(lo), "=f"(hi) : "l"(acc00));
        zs[r0][lane4 + 0] = lo; zs[r0][lane4 + 1] = hi;
        asm("mov.b64 {%0,%1}, %2;" : "=f"(lo), "=f"(hi) : "l"(acc01));
        zs[r0][lane4 + 2] = lo; zs[r0][lane4 + 3] = hi;
        asm("mov.b64 {%0,%1}, %2;" : "=f"(lo), "=f"(hi) : "l"(acc10));
        zs[r0 + 1][lane4 + 0] = lo; zs[r0 + 1][lane4 + 1] = hi;
        asm("mov.b64 {%0,%1}, %2;" : "=f"(lo), "=f"(hi) : "l"(acc11));
        zs[r0 + 1][lane4 + 2] = lo; zs[r0 + 1][lane4 + 3] = hi;
    }
    __syncthreads();

    // ---- gate fusion: 2 (batch,hcol) outputs per thread ----
    #pragma unroll
    for (int i = 0; i < 2; i++) {
        int o = i * 512 + tid;
        int r = o >> 5;
        int hc = o & 31;
        int b_row = m_base + r;
        int h_col = n_base + hc;

        float xv = x[b_row * TSTEPS + t];   // D == 1

        float zi = zs[r][hc]      + fmaf(xv, W[0 * HDIM + h_col], bias[0 * HDIM + h_col]);
        float zj = zs[r][32 + hc] + fmaf(xv, W[1 * HDIM + h_col], bias[1 * HDIM + h_col]);
        float zf = zs[r][64 + hc] + fmaf(xv, W[2 * HDIM + h_col], bias[2 * HDIM + h_col]);
        float zo = zs[r][96 + hc] + fmaf(xv, W[3 * HDIM + h_col], bias[3 * HDIM + h_col]);

        int sidx = b_row * HDIM + h_col;
        float c_old = g_c[sidx];

        float fg = sigmoidf_(zf + 1.0f);
        float ig = sigmoidf_(zi);
        float og = sigmoidf_(zo);
        float c_new = c_old * fg + ig * tanhf(zj);
        float h_new = tanhf(c_new) * og;

        g_c[sidx] = c_new;
        hnext[sidx] = h_new;
        out[(size_t)b_row * (TSTEPS * HDIM) + (size_t)t * HDIM + h_col] = h_new;
    }
}

extern "C" void kernel_launch(void* const* d_in, const int* in_sizes, int n_in,
                              void* d_out, int out_size) {
    const float* x    = (const float*)d_in[0];
    const float* W    = (const float*)d_in[1];
    const float* bias = (const float*)d_in[2];
    float* out = (float*)d_out;
    (void)in_sizes; (void)n_in; (void)out_size;

    lstm_init<<<256, 256>>>();

    dim3 grid(HDIM / 32, BATCH / 32);   // (16, 8) = 128 CTAs
    for (int t = 0; t < TSTEPS; t++) {
        lstm_step<<<grid, 512>>>(x, W, bias, out, t);
    }
}

// round 5
// speedup vs baseline: 2.8105x; 1.7622x over previous
#include <cuda_runtime.h>
#include <cuda_bf16.h>
#include <math.h>
#include <stdint.h>

// LSTM scan: B=256, T=512, D=1, H=512. W:[513,2048] (i,j,f,o). out fp32 [B,T,H].
// Tensor cores via base-PTX mma.sync.m16n8k16 bf16 (sm_103-safe, no tcgen05).
// fp32 emulated: a*w = ahi*whi + ahi*wlo + alo*whi (3-term bf16 split).
// W' precomputed [2048][1536]: n-major, col p = h*4+g, K-stack [Whi|Wlo|Whi].
// Per step: M=256 x N=2048 x K=1536, 128 CTAs (64x64 tiles), 4-deep cp.async ring.

#define BATCH 256
#define TSTEPS 512
#define HDIM 512
#define GDIM 2048
#define KEFF 1536
#define KC 32            // k per chunk (bf16 elems)
#define NCH 48           // KEFF / KC
#define NBUF 4
#define APITCH 80        // bytes per smem row (32*2 + 16 pad)
#define TILEB 5120       // 64 rows * APITCH
#define BUFB  10240      // A tile + B tile
#define ZPITCH 66

__device__ __align__(16) __nv_bfloat16 g_Wp[GDIM * KEFF];      // 6 MB
__device__ __align__(16) __nv_bfloat16 g_A[2][BATCH * 1024];   // hi|lo, ping-pong
__device__ float g_c[BATCH * HDIM];

// ---------- helpers ----------
__device__ __forceinline__ uint32_t cvta_s(const void* p) {
    return (uint32_t)__cvta_generic_to_shared(p);
}
__device__ __forceinline__ void cp16(uint32_t dst, const void* src) {
    asm volatile("cp.async.cg.shared.global [%0], [%1], 16;" :: "r"(dst), "l"(src));
}
#define CP_COMMIT() asm volatile("cp.async.commit_group;")
#define CP_WAIT3()  asm volatile("cp.async.wait_group 3;")

#define LDSM_X4(r0, r1, r2, r3, a)                                             \
    asm volatile("ldmatrix.sync.aligned.m8n8.x4.shared.b16 {%0,%1,%2,%3}, [%4];" \
                 : "=r"(r0), "=r"(r1), "=r"(r2), "=r"(r3) : "r"(a))

#define MMA16816(c, a0, a1, a2, a3, b0, b1)                                    \
    asm volatile("mma.sync.aligned.m16n8k16.row.col.f32.bf16.bf16.f32 "        \
                 "{%0,%1,%2,%3}, {%4,%5,%6,%7}, {%8,%9}, {%0,%1,%2,%3};"       \
                 : "+f"((c)[0]), "+f"((c)[1]), "+f"((c)[2]), "+f"((c)[3])      \
                 : "r"(a0), "r"(a1), "r"(a2), "r"(a3), "r"(b0), "r"(b1))

__device__ __forceinline__ float sigmoidf_(float v) {
    return 1.0f / (1.0f + expf(-v));
}

// ---------- setup ----------
// W'[p][k]: p = h*4 + g  ->  gcol = g*512 + h; k: [0,512)=Whi, [512,1024)=Wlo,
// [1024,1536)=Whi; W row = kk+1 (row 0 is the x weight).
__global__ void conv_w(const float* __restrict__ W) {
    int idx = blockIdx.x * blockDim.x + threadIdx.x;
    if (idx >= GDIM * KEFF) return;
    int p = idx / KEFF;
    int k = idx - p * KEFF;
    int g = p & 3, h = p >> 2;
    int seg = k >> 9, kk = k & 511;
    float w = W[(size_t)(kk + 1) * GDIM + g * HDIM + h];
    __nv_bfloat16 hi = __float2bfloat16(w);
    g_Wp[idx] = (seg == 1) ? __float2bfloat16(w - __bfloat162float(hi)) : hi;
}

__global__ void lstm_init() {
    int i = blockIdx.x * blockDim.x + threadIdx.x;
    if (i < BATCH * HDIM) g_c[i] = 0.0f;
    if (i < BATCH * 1024) {
        g_A[0][i] = __float2bfloat16(0.0f);
        g_A[1][i] = __float2bfloat16(0.0f);
    }
}

// ---------- per-step ----------
// grid (32 nb, 4 mb), 128 threads (4 warps, warp tile 32x32).
__global__ void __launch_bounds__(128, 1) lstm_step(
    const float* __restrict__ x,
    const float* __restrict__ W,
    const float* __restrict__ bias,
    float* __restrict__ out,
    int t)
{
    __shared__ __align__(128) char smem_raw[NBUF * BUFB];   // 40 KB, zs aliases
    __shared__ float s_w0[64], s_b[64];

    const __nv_bfloat16* __restrict__ Ain = g_A[t & 1];
    __nv_bfloat16* __restrict__ Aout = g_A[(t + 1) & 1];

    const int tid = threadIdx.x;
    const int wid = tid >> 5;
    const int lane = tid & 31;
    const int nb = blockIdx.x;             // 0..31 -> h cols nb*16..+16
    const int m_base = blockIdx.y * 64;    // batch tile

    const uint32_t sbase = cvta_s(smem_raw);
    const int warp_m = (wid >> 1) * 32;
    const int warp_n = (wid & 1) * 32;

    if (tid < 64) {
        int gcol = (tid & 3) * HDIM + nb * 16 + (tid >> 2);   // p = h*4+g
        s_w0[tid] = W[gcol];
        s_b[tid] = bias[gcol];
    }

    // global-load coords: 2 A chunks + 2 B chunks of 16B per thread
    const int lm0 = tid >> 2, lc0 = tid & 3;               // q = tid
    const int lm1 = (tid + 128) >> 2, lc1 = (tid + 128) & 3;

    auto prefetch = [&](int c, int buf) {
        int seg = c >> 4;
        int a_off = ((seg == 2) ? 512 : 0) + (c & 15) * KC;
        int w_off = c * KC;
        uint32_t ab = sbase + buf * BUFB;
        uint32_t bb = ab + TILEB;
        cp16(ab + lm0 * APITCH + lc0 * 16,
             &Ain[(size_t)(m_base + lm0) * 1024 + a_off + lc0 * 8]);
        cp16(ab + lm1 * APITCH + lc1 * 16,
             &Ain[(size_t)(m_base + lm1) * 1024 + a_off + lc1 * 8]);
        cp16(bb + lm0 * APITCH + lc0 * 16,
             &g_Wp[(size_t)(nb * 64 + lm0) * KEFF + w_off + lc0 * 8]);
        cp16(bb + lm1 * APITCH + lc1 * 16,
             &g_Wp[(size_t)(nb * 64 + lm1) * KEFF + w_off + lc1 * 8]);
    };

    float acc[2][4][4] = {};

    prefetch(0, 0); CP_COMMIT();
    prefetch(1, 1); CP_COMMIT();
    prefetch(2, 2); CP_COMMIT();
    prefetch(3, 3); CP_COMMIT();

    // ldmatrix per-lane address components
    const uint32_t a_row = warp_m + (lane & 15);
    const uint32_t a_colb = (lane >> 4) * 16;
    const uint32_t b_row = warp_n + (lane & 7) + ((lane >> 4) << 3);
    const uint32_t b_colb = ((lane >> 3) & 1) * 16;

    #pragma unroll 1
    for (int c = 0; c < NCH; c++) {
        const int buf = c & 3;
        CP_WAIT3();              // with the always-commit invariant: chunk c ready
        __syncthreads();

        const uint32_t ab = sbase + buf * BUFB;
        const uint32_t bb = ab + TILEB;

        #pragma unroll
        for (int ks = 0; ks < 2; ks++) {
            uint32_t a0, a1, a2, a3, a4, a5, a6, a7;
            uint32_t b00, b01, b10, b11, b20, b21, b30, b31;
            uint32_t aaddr = ab + a_row * APITCH + ks * 32 + a_colb;
            LDSM_X4(a0, a1, a2, a3, aaddr);
            LDSM_X4(a4, a5, a6, a7, aaddr + 16 * APITCH);
            uint32_t baddr = bb + b_row * APITCH + ks * 32 + b_colb;
            LDSM_X4(b00, b01, b10, b11, baddr);
            LDSM_X4(b20, b21, b30, b31, baddr + 16 * APITCH);

            MMA16816(acc[0][0], a0, a1, a2, a3, b00, b01);
            MMA16816(acc[0][1], a0, a1, a2, a3, b10, b11);
            MMA16816(acc[0][2], a0, a1, a2, a3, b20, b21);
            MMA16816(acc[0][3], a0, a1, a2, a3, b30, b31);
            MMA16816(acc[1][0], a4, a5, a6, a7, b00, b01);
            MMA16816(acc[1][1], a4, a5, a6, a7, b10, b11);
            MMA16816(acc[1][2], a4, a5, a6, a7, b20, b21);
            MMA16816(acc[1][3], a4, a5, a6, a7, b30, b31);
        }
        __syncthreads();
        if (c + 4 < NCH) prefetch(c + 4, buf);
        CP_COMMIT();             // empty-group commit keeps wait_group 3 exact
    }

    // ---- z stage (alias smem buffers) ----
    __syncthreads();
    float* zs = (float*)smem_raw;   // [64][ZPITCH]
    #pragma unroll
    for (int mf = 0; mf < 2; mf++)
        #pragma unroll
        for (int nf = 0; nf < 4; nf++) {
            int row = warp_m + mf * 16 + (lane >> 2);
            int col = warp_n + nf * 8 + (lane & 3) * 2;
            *(float2*)&zs[row * ZPITCH + col] =
                make_float2(acc[mf][nf][0], acc[mf][nf][1]);
            *(float2*)&zs[(row + 8) * ZPITCH + col] =
                make_float2(acc[mf][nf][2], acc[mf][nf][3]);
        }
    __syncthreads();

    // ---- gate fusion: 8 (batch,h) outputs per thread ----
    #pragma unroll
    for (int i = 0; i < 8; i++) {
        int o = i * 128 + tid;
        int r = o >> 4;             // local batch row
        int h = o & 15;             // local h col
        int b_row = m_base + r;
        int h_col = nb * 16 + h;

        float xv = x[b_row * TSTEPS + t];   // D == 1
        const float* z4 = &zs[r * ZPITCH + h * 4];

        float zi = z4[0] + fmaf(xv, s_w0[h * 4 + 0], s_b[h * 4 + 0]);
        float zj = z4[1] + fmaf(xv, s_w0[h * 4 + 1], s_b[h * 4 + 1]);
        float zf = z4[2] + fmaf(xv, s_w0[h * 4 + 2], s_b[h * 4 + 2]);
        float zo = z4[3] + fmaf(xv, s_w0[h * 4 + 3], s_b[h * 4 + 3]);

        int sidx = b_row * HDIM + h_col;
        float c_old = g_c[sidx];
        float fg = sigmoidf_(zf + 1.0f);
        float ig = sigmoidf_(zi);
        float og = sigmoidf_(zo);
        float cn = c_old * fg + ig * tanhf(zj);
        float hn = tanhf(cn) * og;

        g_c[sidx] = cn;
        out[(size_t)b_row * (TSTEPS * HDIM) + (size_t)t * HDIM + h_col] = hn;
        __nv_bfloat16 hi = __float2bfloat16(hn);
        __nv_bfloat16 lo = __float2bfloat16(hn - __bfloat162float(hi));
        Aout[(size_t)b_row * 1024 + h_col] = hi;
        Aout[(size_t)b_row * 1024 + 512 + h_col] = lo;
    }
}

extern "C" void kernel_launch(void* const* d_in, const int* in_sizes, int n_in,
                              void* d_out, int out_size) {
    const float* x    = (const float*)d_in[0];
    const float* W    = (const float*)d_in[1];
    const float* bias = (const float*)d_in[2];
    float* out = (float*)d_out;
    (void)in_sizes; (void)n_in; (void)out_size;

    conv_w<<<(GDIM * KEFF + 255) / 256, 256>>>(W);
    lstm_init<<<(BATCH * 1024 + 255) / 256, 256>>>();

    dim3 grid(32, 4);   // 32 N-tiles x 4 M-tiles = 128 CTAs
    for (int t = 0; t < TSTEPS; t++) {
        lstm_step<<<grid, 128>>>(x, W, bias, out, t);
    }
}